// round 14
// baseline (speedup 1.0000x reference)
#include <cuda_runtime.h>
#include <cuda_bf16.h>
#include <math.h>

#define BATCH   512
#define T_STEPS 512
#define CHAN    32
#define CIN     33
#define HID     128
#define GATES   512   // 4*H
#define EPSF    1e-12f

typedef unsigned long long ull_t;
typedef unsigned int u32_t;

// ---------------------------------------------------------------------------
// f32x2 packed-math helpers (Blackwell FFMA2 path — only reachable via PTX)
// ---------------------------------------------------------------------------
__device__ __forceinline__ void ffma2(ull_t& d, ull_t a, ull_t b) {
    asm("fma.rn.f32x2 %0, %1, %2, %0;" : "+l"(d) : "l"(a), "l"(b));
}
// (bf16_lo, bf16_hi) packed in u32 -> (f32_lo, f32_hi) packed b64 (pure ALU)
__device__ __forceinline__ ull_t bf2_to_f32x2(u32_t u) {
    ull_t r;
    asm("{\n\t.reg .b32 lo, hi;\n\t"
        "shl.b32 lo, %1, 16;\n\t"
        "and.b32 hi, %1, 0xFFFF0000;\n\t"
        "mov.b64 %0, {lo, hi};\n\t}" : "=l"(r) : "r"(u));
    return r;
}
__device__ __forceinline__ ull_t pack_dup(float v) {
    ull_t r; u32_t b = __float_as_uint(v);
    asm("mov.b64 %0, {%1, %1};" : "=l"(r) : "r"(b));
    return r;
}
__device__ __forceinline__ float2 unpack2(ull_t d) {
    u32_t lo, hi;
    asm("mov.b64 {%0, %1}, %2;" : "=r"(lo), "=r"(hi) : "l"(d));
    return make_float2(__uint_as_float(lo), __uint_as_float(hi));
}
__device__ __forceinline__ float hsum2(ull_t d) {
    float2 f = unpack2(d); return f.x + f.y;
}
__device__ __forceinline__ u32_t pack_bf2(float a, float b) {
    u32_t ua = (u32_t)__bfloat16_as_ushort(__float2bfloat16(a));
    u32_t ub = (u32_t)__bfloat16_as_ushort(__float2bfloat16(b));
    return ua | (ub << 16);
}
__device__ __forceinline__ ull_t pack2(float a, float b) {
    ull_t r;
    asm("mov.b64 %0, {%1, %2};" : "=l"(r)
        : "r"(__float_as_uint(a)), "r"(__float_as_uint(b)));
    return r;
}

// ---------------------------------------------------------------------------
// Device scratch (static; allocations are forbidden)
// ---------------------------------------------------------------------------
__device__ float g_std_arr[T_STEPS];             // minibatch-std scalar per t
__device__ float g_inv_arr[4];                   // 1/sigma: ih, hh, fc
__device__ float g_wt[CIN * GATES];              // Wih^T scaled: [33][512]
__device__ float g_bias[GATES];                  // b_ih + b_hh
__device__ u32_t g_whh_p[(HID / 2) * GATES];     // bf16 k-pairs, k2-major [64][512]
__device__ float g_gates[(size_t)BATCH * T_STEPS * GATES]; // 536 MB gates_x

// ---------------------------------------------------------------------------
// Kernel A: minibatch std feature. grid=T, block=256 (8 b-seg x 32 chan)
// ---------------------------------------------------------------------------
__global__ void std_kernel(const float* __restrict__ x)
{
    int t   = blockIdx.x;
    int tid = threadIdx.x;
    int c   = tid & 31;
    int seg = tid >> 5;

    float s = 0.f, ss = 0.f;
    for (int b = seg; b < BATCH; b += 8) {
        float v = x[((size_t)b * T_STEPS + t) * CHAN + c];
        s  += v;
        ss += v * v;
    }
    __shared__ float sm1[256], sm2[256];
    sm1[tid] = s; sm2[tid] = ss;
    __syncthreads();
    if (seg == 0) {
        for (int k = 1; k < 8; k++) { s += sm1[k * 32 + c]; ss += sm2[k * 32 + c]; }
        float mean = s * (1.f / 512.f);
        float var  = (ss - 512.f * mean * mean) * (1.f / 511.f);
        float sd   = sqrtf(fmaxf(var, 0.f));
        #pragma unroll
        for (int off = 16; off; off >>= 1)
            sd += __shfl_xor_sync(0xffffffffu, sd, off);
        if (c == 0) g_std_arr[t] = sd * (1.f / 32.f);
    }
}

// ---------------------------------------------------------------------------
// Kernel B: spectral norms (one power iteration, matching reference exactly)
// then scale+transpose Wih, combine bias, quantize Whh to bf16 k-pairs.
// single block, 512 threads
// ---------------------------------------------------------------------------
__global__ void prep_kernel(const float* __restrict__ wih, const float* __restrict__ uih,
                            const float* __restrict__ whh, const float* __restrict__ uhh,
                            const float* __restrict__ bih, const float* __restrict__ bhh,
                            const float* __restrict__ wfc, const float* __restrict__ ufc)
{
    __shared__ float tv[HID];
    __shared__ float red[512];
    __shared__ float nrm;
    __shared__ float inv_s[4];
    int tid = threadIdx.x;

    // ---- ih: W [512,33] ----
    if (tid < CIN) {
        float s = 0.f;
        for (int g = 0; g < GATES; g++) s += wih[g * CIN + tid] * uih[g];
        tv[tid] = s;
    }
    __syncthreads();
    if (tid == 0) {
        float n = 0.f;
        for (int c = 0; c < CIN; c++) n += tv[c] * tv[c];
        nrm = sqrtf(n) + EPSF;
    }
    __syncthreads();
    {
        float a = 0.f;
        for (int c = 0; c < CIN; c++) a += wih[tid * CIN + c] * tv[c];
        a /= nrm;
        red[tid] = a * a;
    }
    __syncthreads();
    for (int off = 256; off; off >>= 1) {
        if (tid < off) red[tid] += red[tid + off];
        __syncthreads();
    }
    if (tid == 0) {
        float ssum = red[0];                      // ||W v||^2
        float v = (sqrtf(ssum) + EPSF) / ssum;    // 1/sigma
        g_inv_arr[0] = v; inv_s[0] = v;
    }
    __syncthreads();

    // ---- hh: W [512,128] ----
    if (tid < HID) {
        float s = 0.f;
        for (int g = 0; g < GATES; g++) s += whh[g * HID + tid] * uhh[g];
        tv[tid] = s;
    }
    __syncthreads();
    if (tid == 0) {
        float n = 0.f;
        for (int k = 0; k < HID; k++) n += tv[k] * tv[k];
        nrm = sqrtf(n) + EPSF;
    }
    __syncthreads();
    {
        float a = 0.f;
        for (int k = 0; k < HID; k++) a += whh[tid * HID + k] * tv[k];
        a /= nrm;
        red[tid] = a * a;
    }
    __syncthreads();
    for (int off = 256; off; off >>= 1) {
        if (tid < off) red[tid] += red[tid + off];
        __syncthreads();
    }
    if (tid == 0) {
        float ssum = red[0];
        float v = (sqrtf(ssum) + EPSF) / ssum;
        g_inv_arr[1] = v; inv_s[1] = v;
    }
    __syncthreads();

    // ---- fc: W [1,128] ----
    red[tid] = (tid < HID) ? wfc[tid] * wfc[tid] : 0.f;
    __syncthreads();
    for (int off = 256; off; off >>= 1) {
        if (tid < off) red[tid] += red[tid + off];
        __syncthreads();
    }
    if (tid == 0) {
        float wn2 = red[0];
        float u0  = ufc[0];
        float tn  = fabsf(u0) * sqrtf(wn2) + EPSF;   // ||W^T u||
        float s   = u0 * wn2 / tn;                   // W @ v (scalar)
        float sig = s * s / (fabsf(s) + EPSF);
        float v = 1.f / sig;
        g_inv_arr[2] = v; inv_s[2] = v;
    }
    __syncthreads();

    // ---- scale + pack ----
    float i0 = inv_s[0], i1 = inv_s[1];
    // Wih transposed & scaled: g_wt[c*512+g]
    for (int c = 0; c < CIN; c++)
        g_wt[c * GATES + tid] = wih[tid * CIN + c] * i0;
    g_bias[tid] = bih[tid] + bhh[tid];
    // Whh scaled -> bf16 k-pairs, k2-major: g_whh_p[k2*512 + g]
    for (int k2 = 0; k2 < HID / 2; k2++) {
        float we = whh[tid * HID + 2 * k2]     * i1;
        float wo = whh[tid * HID + 2 * k2 + 1] * i1;
        g_whh_p[k2 * GATES + tid] = pack_bf2(we, wo);
    }
}

// ---------------------------------------------------------------------------
// Kernel C: gates_x = x_aug @ Wih_n^T + bias (f32x2 packed over gate pairs).
// grid = 8192 blocks x 32 rows, 256 threads; thread t owns gates (2t, 2t+1).
// ---------------------------------------------------------------------------
__global__ void gates_kernel(const float* __restrict__ x)
{
    __shared__ ull_t xs_d[CIN * 34];   // x duplicated (v,v), [c][34 rows]
    int row0 = blockIdx.x * 32;
    int tid  = threadIdx.x;

    for (int i = tid; i < 32 * CHAN; i += 256) {
        int r = i >> 5, c = i & 31;
        xs_d[c * 34 + r] = pack_dup(x[(size_t)(row0 + r) * CHAN + c]);
    }
    if (tid < 32)
        xs_d[CHAN * 34 + tid] = pack_dup(g_std_arr[(row0 + tid) & (T_STEPS - 1)]);
    __syncthreads();

    const ull_t* wt2   = (const ull_t*)g_wt;     // (w_2t, w_2t+1) f32 pairs
    const ull_t* bias2 = (const ull_t*)g_bias;
    ull_t*       gout  = (ull_t*)g_gates;
    ull_t bp = bias2[tid];

    for (int rb = 0; rb < 32; rb += 8) {
        ull_t acc[8];
        #pragma unroll
        for (int r = 0; r < 8; r++) acc[r] = bp;
        #pragma unroll
        for (int c = 0; c < CIN; c++) {
            ull_t w = wt2[c * (GATES / 2) + tid];
            #pragma unroll
            for (int r = 0; r < 8; r++)
                ffma2(acc[r], w, xs_d[c * 34 + rb + r]);
        }
        #pragma unroll
        for (int r = 0; r < 8; r++)
            gout[(size_t)(row0 + rb + r) * (GATES / 2) + tid] = acc[r];
    }
}

// ---------------------------------------------------------------------------
// Kernel D: persistent LSTM + online-softmax attention + FC epilogue.
// 128 blocks x 4 batch rows, 256 threads, 512 steps.
// R12-proven structure; this round: LDS.128 for h (k4-granular, 128 loads
// vs 256) and LDS.128 (ull2) for the smem weight half (16 loads vs 32).
// Hybrid weights: k2 0..31 in 64 regs, k2 32..63 in smem (interleaved per k4).
// Two barriers/step, exp-form activations, softmax state in registers.
// ---------------------------------------------------------------------------
__global__ void __launch_bounds__(256, 1)
lstm_kernel(const float* __restrict__ attn_w,
            const float* __restrict__ fc_w,
            const float* __restrict__ fc_b,
            float* __restrict__ out)
{
    extern __shared__ __align__(16) unsigned char smem_raw[];
    ulonglong2* wsm2 = (ulonglong2*)smem_raw;      // [16 k4][256]: {pair(2k4), pair(2k4+1)}

    __shared__ __align__(16) float h_s[4 * HID];   // [4][128]
    __shared__ float gts[4 * GATES];               // [4][512]
    __shared__ float aw_s[HID];
    __shared__ float fw_s[HID];
    __shared__ float lpart[2][8];                  // [slot][warp] attn partials

    int tid  = threadIdx.x;
    int b0   = blockIdx.x * 4;
    int wid  = tid >> 5, lane = tid & 31;
    int r0   = tid >> 7;          // slot0 row (0..1); slot1 row = r0+2
    int j0   = tid & 127;         // hidden index for both slots

    const ull_t* gwp = (const ull_t*)g_whh_p;      // [64 k2][256] ull (gate pairs)

    // weights: k2 0..31 into registers (64 regs); k4 16..31 into smem as ull2
    ull_t wreg[32];
    #pragma unroll
    for (int k2 = 0; k2 < 32; k2++)
        wreg[k2] = gwp[k2 * (GATES / 2) + tid];
    for (int i = tid; i < 16 * (GATES / 2); i += 256) {
        int k4l = i >> 8, t = i & 255;             // local k4 0..15 -> global 16+k4l
        ulonglong2 v;
        v.x = gwp[(32 + 2 * k4l) * (GATES / 2) + t];
        v.y = gwp[(33 + 2 * k4l) * (GATES / 2) + t];
        wsm2[i] = v;
    }

    for (int i = tid; i < 4 * HID; i += 256) h_s[i] = 0.f;
    if (tid < HID) { aw_s[tid] = attn_w[tid]; fw_s[tid] = fc_w[tid]; }
    __syncthreads();

    float cst[2]  = {0.f, 0.f};           // cell state per slot
    float accp[2] = {0.f, 0.f};           // online pooled accumulator per slot
    float mloc[2] = {-INFINITY, -INFINITY};
    float sloc[2] = {0.f, 0.f};

    const float4* h4   = (const float4*)h_s;       // [4][32] float4 (k4-granular)
    const ull_t*  gsrc = (const ull_t*)g_gates;
    ull_t*        gts2 = (ull_t*)gts;

    for (int t = 0; t < T_STEPS; t++) {
        // prefetch gates_x pairs (coalesced; latency hidden under the matvec)
        ull_t gx[4];
        #pragma unroll
        for (int r = 0; r < 4; r++)
            gx[r] = gsrc[((size_t)(b0 + r) * T_STEPS + t) * (GATES / 2) + tid];

        // gates += h @ Whh^T  (acc = (sum_even_k, sum_odd_k) per gate)
        ull_t a0[4] = {0, 0, 0, 0};   // gate 2t
        ull_t a1[4] = {0, 0, 0, 0};   // gate 2t+1
        #pragma unroll
        for (int k4 = 0; k4 < 16; k4++) {           // register half (k2 0..31)
            float2 wbA = unpack2(wreg[2 * k4]);     // k2 = 2k4
            float2 wbB = unpack2(wreg[2 * k4 + 1]); // k2 = 2k4+1
            ull_t w0A = bf2_to_f32x2(__float_as_uint(wbA.x));
            ull_t w1A = bf2_to_f32x2(__float_as_uint(wbA.y));
            ull_t w0B = bf2_to_f32x2(__float_as_uint(wbB.x));
            ull_t w1B = bf2_to_f32x2(__float_as_uint(wbB.y));
            #pragma unroll
            for (int r = 0; r < 4; r++) {
                float4 hv = h4[r * (HID / 4) + k4]; // LDS.128 broadcast
                ull_t h01 = pack2(hv.x, hv.y);
                ull_t h23 = pack2(hv.z, hv.w);
                ffma2(a0[r], w0A, h01);
                ffma2(a1[r], w1A, h01);
                ffma2(a0[r], w0B, h23);
                ffma2(a1[r], w1B, h23);
            }
        }
        #pragma unroll 8
        for (int k4 = 16; k4 < 32; k4++) {          // smem half (k2 32..63)
            ulonglong2 wp = wsm2[(k4 - 16) * (GATES / 2) + tid];   // LDS.128
            float2 wbA = unpack2(wp.x);
            float2 wbB = unpack2(wp.y);
            ull_t w0A = bf2_to_f32x2(__float_as_uint(wbA.x));
            ull_t w1A = bf2_to_f32x2(__float_as_uint(wbA.y));
            ull_t w0B = bf2_to_f32x2(__float_as_uint(wbB.x));
            ull_t w1B = bf2_to_f32x2(__float_as_uint(wbB.y));
            #pragma unroll
            for (int r = 0; r < 4; r++) {
                float4 hv = h4[r * (HID / 4) + k4];
                ull_t h01 = pack2(hv.x, hv.y);
                ull_t h23 = pack2(hv.z, hv.w);
                ffma2(a0[r], w0A, h01);
                ffma2(a1[r], w1A, h01);
                ffma2(a0[r], w0B, h23);
                ffma2(a1[r], w1B, h23);
            }
        }
        #pragma unroll
        for (int r = 0; r < 4; r++) {
            float2 gxf = unpack2(gx[r]);
            gts2[r * (GATES / 2) + tid] =
                pack2(hsum2(a0[r]) + gxf.x, hsum2(a1[r]) + gxf.y);  // STS.64
        }
        __syncthreads();                            // sync1: gates ready

        // pointwise LSTM cell, 2 slots/thread; exp-based activations
        float hv2[2];
        #pragma unroll
        for (int p = 0; p < 2; p++) {
            int r = r0 + 2 * p;
            const float* gr = &gts[r * GATES];
            float gi = gr[j0], gf = gr[HID + j0];
            float gg = gr[2 * HID + j0], go = gr[3 * HID + j0];
            float iv = 1.f / (1.f + __expf(-gi));
            float fv = 1.f / (1.f + __expf(-gf));
            float gv = 2.f / (1.f + __expf(-2.f * gg)) - 1.f;   // tanh
            float ov = 1.f / (1.f + __expf(-go));
            float c  = fv * cst[p] + iv * gv;
            cst[p]   = c;
            float hv = ov * (2.f / (1.f + __expf(-2.f * c)) - 1.f);
            hv2[p]   = hv;
            h_s[r * HID + j0] = hv;
        }

        // attention partials: per (warp, slot) a clean 32-j segment of one row
        #pragma unroll
        for (int p = 0; p < 2; p++) {
            float part = hv2[p] * aw_s[j0];
            #pragma unroll
            for (int off = 16; off; off >>= 1)
                part += __shfl_xor_sync(0xffffffffu, part, off);
            if (lane == 0) lpart[p][wid] = part;
        }
        __syncthreads();                            // sync2: h + partials ready

        // online softmax, state in registers (redundant across a row's threads)
        #pragma unroll
        for (int p = 0; p < 2; p++) {
            int r  = r0 + 2 * p;                    // row of this slot
            int ws = 4 * (r & 1);                   // warps holding this row
            float l = lpart[p][ws] + lpart[p][ws + 1]
                    + lpart[p][ws + 2] + lpart[p][ws + 3];
            float mnew = fmaxf(mloc[p], l);
            float al   = __expf(mloc[p] - mnew);    // 0 on first step
            float pv   = __expf(l - mnew);
            mloc[p] = mnew;
            sloc[p] = sloc[p] * al + pv;
            accp[p] = accp[p] * al + pv * hv2[p];
        }
        // hazards: h_s written pre-sync2, read by matvec(t+1) post-sync2 ✓;
        // gts read pre-sync2, rewritten post-sync2 ✓; lpart read here post-
        // sync2, next written post-sync1(t+1) ✓. Two barriers/step suffice.
    }

    // epilogue: pooled = acc/s ; score = pooled . (fc_w/sigma) + fc_b
    __syncthreads();                                // lpart reads done, reuse
    #pragma unroll
    for (int p = 0; p < 2; p++) {
        float po   = accp[p] / sloc[p];
        float part = po * fw_s[j0];
        #pragma unroll
        for (int off = 16; off; off >>= 1)
            part += __shfl_xor_sync(0xffffffffu, part, off);
        if (lane == 0) lpart[p][wid] = part;
    }
    __syncthreads();
    if (tid < 4) {
        int p  = tid >> 1;                          // slot that owns row tid
        int ws = 4 * (tid & 1);
        float sc = lpart[p][ws] + lpart[p][ws + 1]
                 + lpart[p][ws + 2] + lpart[p][ws + 3];
        out[b0 + tid] = sc * g_inv_arr[2] + fc_b[0];
    }
}

// ---------------------------------------------------------------------------
extern "C" void kernel_launch(void* const* d_in, const int* in_sizes, int n_in,
                              void* d_out, int out_size)
{
    const float* x      = (const float*)d_in[0];
    const float* w_ih   = (const float*)d_in[1];
    const float* u_ih   = (const float*)d_in[2];
    const float* w_hh   = (const float*)d_in[3];
    const float* u_hh   = (const float*)d_in[4];
    const float* b_ih   = (const float*)d_in[5];
    const float* b_hh   = (const float*)d_in[6];
    const float* attn_w = (const float*)d_in[7];
    // d_in[8] = attn_b (softmax shift-invariant, unused)
    const float* fc_w   = (const float*)d_in[9];
    const float* u_fc   = (const float*)d_in[10];
    const float* fc_b   = (const float*)d_in[11];
    float* out = (float*)d_out;

    std_kernel<<<T_STEPS, 256>>>(x);
    prep_kernel<<<1, 512>>>(w_ih, u_ih, w_hh, u_hh, b_ih, b_hh, fc_w, u_fc);
    gates_kernel<<<(BATCH * T_STEPS) / 32, 256>>>(x);

    int smem = 16 * (GATES / 2) * 16;   // 64 KB dynamic: smem half of Whh (ull2)
    cudaFuncSetAttribute(lstm_kernel, cudaFuncAttributeMaxDynamicSharedMemorySize, smem);
    lstm_kernel<<<BATCH / 4, 256, smem>>>(attn_w, fc_w, fc_b, out);
}